// round 16
// baseline (speedup 1.0000x reference)
#include <cuda_runtime.h>
#include <cuda_fp16.h>
#include <cstdint>

#define Bq    8
#define CIN   128
#define COUT  128
#define HH    256
#define WW    256
#define SDIM  512

#define PXW   68     // words (half2) per px row: 64 used + 4 pad; 4*gid+tig mod 32 -> conflict-free
#define NPX   258    // 256 px + 2 halo

__device__ float  g_style[Bq * CIN];
__device__ float  g_demod[Bq * COUT];
__device__ float  g_W2[COUT * CIN];
__device__ __half g_wA[36 * 4096];   // fragment-ordered fp16 weights (exact size, OOB fixed)

#define MMA_F16(d, a, bb)                                                 \
    asm volatile("mma.sync.aligned.m16n8k16.row.col.f32.f16.f16.f32 "     \
                 "{%0,%1,%2,%3}, {%4,%5,%6,%7}, {%8,%9}, {%0,%1,%2,%3};"  \
                 : "+f"((d)[0]), "+f"((d)[1]), "+f"((d)[2]), "+f"((d)[3]) \
                 : "r"((a)[0]), "r"((a)[1]), "r"((a)[2]), "r"((a)[3]),    \
                   "r"((bb)[0]), "r"((bb)[1]))

// ---------------------------------------------------------------------------
// prep1: blocks 0..127 style GEMV; 128..191 W2; 192..767 weight prepack.
// ---------------------------------------------------------------------------
__global__ void prep1(const float* __restrict__ w,
                      const float* __restrict__ style_W,
                      const float* __restrict__ style_b,
                      const float* __restrict__ weight) {
    if (blockIdx.x < 128) {
        const int gw   = blockIdx.x * 8 + (threadIdx.x >> 5);
        const int lane = threadIdx.x & 31;
        const int b = gw >> 7, o = gw & 127;
        const float4* wv = (const float4*)(w + (size_t)b * SDIM);
        const float4* Wv = (const float4*)(style_W + (size_t)o * SDIM);
        float acc = 0.f;
        #pragma unroll
        for (int k = 0; k < 4; k++) {
            float4 a = wv[lane + k * 32], c = Wv[lane + k * 32];
            acc += a.x * c.x + a.y * c.y + a.z * c.z + a.w * c.w;
        }
        #pragma unroll
        for (int d = 16; d > 0; d >>= 1)
            acc += __shfl_xor_sync(0xffffffffu, acc, d);
        if (lane == 0) g_style[b * CIN + o] = acc + style_b[o];
    } else if (blockIdx.x < 192) {
        int idx = (blockIdx.x - 128) * 256 + threadIdx.x;
        const float* p = weight + (size_t)idx * 9;
        float s = 0.f;
        #pragma unroll
        for (int t = 0; t < 9; t++) { float v = p[t]; s += v * v; }
        g_W2[idx] = s;
    } else {
        int idx = (blockIdx.x - 192) * 256 + threadIdx.x;   // < 147456
        int h    = idx & 1;
        int j    = (idx >> 1) & 3;
        int lane = (idx >> 3) & 31;
        int mt   = (idx >> 8) & 7;
        int kk   = (idx >> 11) & 1;
        int s    = idx >> 12;                               // 0..35 (exact)
        int dx = s % 3;
        int g  = s / 3;
        int dy = g >> 2, chunk = g & 3;
        int m  = mt * 16 + (lane >> 2) + 8 * (j & 1);
        int kl = kk * 16 + (lane & 3) * 2 + 8 * (j >> 1) + h;
        int c  = chunk * 32 + kl;
        g_wA[idx] = __float2half_rn(weight[((size_t)m * CIN + c) * 9 + dy * 3 + dx]);
    }
}

// ---------------------------------------------------------------------------
// prep2: demod only
// ---------------------------------------------------------------------------
__global__ void prep2(void) {
    int gw   = blockIdx.x * 8 + (threadIdx.x >> 5);
    int lane = threadIdx.x & 31;
    int b = gw >> 7, o = gw & 127;
    float sum = 0.f;
    #pragma unroll
    for (int j = 0; j < 4; j++) {
        int i = lane + j * 32;
        float s = g_style[b * CIN + i];
        sum += s * s * g_W2[o * CIN + i];
    }
    #pragma unroll
    for (int d = 16; d > 0; d >>= 1)
        sum += __shfl_xor_sync(0xffffffffu, sum, d);
    if (lane == 0) g_demod[b * COUT + o] = rsqrtf(sum + 1e-8f);
}

// ---------------------------------------------------------------------------
// main conv: CTA = (y, b). M=128 x N=256 x K=1152, fp16 m16n8k16.
// 16 warps = 2(wm: 64oc) x 8(wn: 32px). 3 dy-groups, full 128 channels each.
// A-fragments software-pipelined one kk ahead. Halved A L2 traffic vs R15.
// ---------------------------------------------------------------------------
__global__ __launch_bounds__(512, 1)
void conv_mma_kernel(const float* __restrict__ x,
                     const float* __restrict__ bias,
                     float* __restrict__ out) {
    __shared__ float    styl[CIN];
    __shared__ uint32_t stage[2][NPX * PXW];

    const int tid  = threadIdx.x;
    const int lane = tid & 31;
    const int warp = tid >> 5;
    const int wm   = warp >> 3;      // 0..1
    const int wn   = warp & 7;       // 0..7
    const int y    = blockIdx.x;
    const int b    = blockIdx.y;

    const int gid = lane >> 2;       // 0..7
    const int tig = lane & 3;        // 0..3

    if (tid < CIN) styl[tid] = g_style[b * CIN + tid];
    __syncthreads();

    float acc[4][4][4];
    #pragma unroll
    for (int m = 0; m < 4; m++)
        #pragma unroll
        for (int n = 0; n < 4; n++)
            #pragma unroll
            for (int j = 0; j < 4; j++) acc[m][n][j] = 0.f;

    // fill mapping: px = jj*128 + (tid>>2), cp = (tid&3) + 4*ii (ii 0..15)
    const int fpx = tid >> 2;        // 0..127
    const int fc  = tid & 3;
    // tail px 256,257 x 64 cp: warps 0..3
    const int tpx = 256 + (warp >> 1);
    const int tcp = (warp & 1) * 32 + lane;

    // ---- fill one stage buffer for group dy: 128 ch x 258 px ----
    auto fill = [&](int dy, uint32_t* buf) {
        const int yr = y + dy - 1;
        const bool yok = (unsigned)yr < (unsigned)HH;
        const float* xp = x + (((size_t)b * CIN) * HH + yr) * WW;
        #pragma unroll
        for (int jj = 0; jj < 2; jj++) {
            const int px = jj * 128 + fpx;
            const int gx = px - 1;
            const bool ok = yok && ((unsigned)gx < (unsigned)WW);
            #pragma unroll
            for (int ii = 0; ii < 16; ii++) {
                const int cp = fc + ii * 4;
                float v0 = 0.f, v1 = 0.f;
                if (ok) {
                    v0 = __ldg(xp + (size_t)(2 * cp)     * HH * WW + gx) * styl[2 * cp];
                    v1 = __ldg(xp + (size_t)(2 * cp + 1) * HH * WW + gx) * styl[2 * cp + 1];
                }
                __half2 hv = __floats2half2_rn(v0, v1);
                buf[px * PXW + cp] = *(uint32_t*)&hv;
            }
        }
        if (warp < 4) {
            const int gx = tpx - 1;
            float v0 = 0.f, v1 = 0.f;
            if (yok && gx < WW) {
                v0 = __ldg(xp + (size_t)(2 * tcp)     * HH * WW + gx) * styl[2 * tcp];
                v1 = __ldg(xp + (size_t)(2 * tcp + 1) * HH * WW + gx) * styl[2 * tcp + 1];
            }
            __half2 hv = __floats2half2_rn(v0, v1);
            buf[tpx * PXW + tcp] = *(uint32_t*)&hv;
        }
    };

    // A-fragment pointer for (dy, dx, kk)
    auto Aptr = [&](int dy, int dx, int kk) -> const uint4* {
        const int s = (dy * 4 + (kk >> 1)) * 3 + dx;
        return ((const uint4*)g_wA) +
               (((size_t)(s * 2 + (kk & 1)) * 8 + wm * 4) * 32 + lane);
    };

    // ---- one dx-step: A-fragments prefetched one kk ahead ----
    auto compute = [&](const uint32_t* stg, int dy, int dx) {
        uint4 af[4];
        {
            const uint4* As = Aptr(dy, dx, 0);
            #pragma unroll
            for (int m = 0; m < 4; m++) af[m] = __ldg(As + m * 32);
        }
        #pragma unroll
        for (int kk = 0; kk < 8; kk++) {
            uint4 afn[4];
            if (kk < 7) {
                const uint4* As = Aptr(dy, dx, kk + 1);
                #pragma unroll
                for (int m = 0; m < 4; m++) afn[m] = __ldg(As + m * 32);
            }
            uint32_t bb[4][2];
            #pragma unroll
            for (int n = 0; n < 4; n++) {
                const int px = wn * 32 + n * 8 + gid + dx;
                const uint32_t* p = stg + px * PXW + kk * 8 + tig;
                bb[n][0] = p[0];
                bb[n][1] = p[4];
            }
            #pragma unroll
            for (int m = 0; m < 4; m++) {
                const uint32_t* a = (const uint32_t*)&af[m];
                #pragma unroll
                for (int n = 0; n < 4; n++)
                    MMA_F16(acc[m][n], a, bb[n]);
            }
            if (kk < 7) {
                #pragma unroll
                for (int m = 0; m < 4; m++) af[m] = afn[m];
            }
        }
    };

    fill(0, stage[0]);
    __syncthreads();

    #pragma unroll 1
    for (int G = 0; G < 3; G++) {
        const int cur = G & 1;
        compute(stage[cur], G, 0);
        if (G < 2) fill(G + 1, stage[cur ^ 1]);   // LDG in flight across dx=1,2
        compute(stage[cur], G, 1);
        compute(stage[cur], G, 2);
        if (G < 2) __syncthreads();
    }

    // ---- epilogue: demod + bias, float2 stores ----
    #pragma unroll
    for (int m = 0; m < 4; m++) {
        const int oc0 = (wm * 4 + m) * 16 + gid;
        const int oc1 = oc0 + 8;
        const float d0 = g_demod[b * COUT + oc0], bb0 = bias[oc0];
        const float d1 = g_demod[b * COUT + oc1], bb1 = bias[oc1];
        float* r0 = out + (((size_t)b * COUT + oc0) * HH + y) * WW;
        float* r1 = out + (((size_t)b * COUT + oc1) * HH + y) * WW;
        #pragma unroll
        for (int n = 0; n < 4; n++) {
            const int px = (wn * 4 + n) * 8 + tig * 2;
            float2 v0 = make_float2(acc[m][n][0] * d0 + bb0, acc[m][n][1] * d0 + bb0);
            float2 v1 = make_float2(acc[m][n][2] * d1 + bb1, acc[m][n][3] * d1 + bb1);
            *(float2*)(r0 + px) = v0;
            *(float2*)(r1 + px) = v1;
        }
    }
}

// ---------------------------------------------------------------------------
extern "C" void kernel_launch(void* const* d_in, const int* in_sizes, int n_in,
                              void* d_out, int out_size) {
    const float* x       = (const float*)d_in[0];
    const float* w       = (const float*)d_in[1];
    const float* weight  = (const float*)d_in[2];
    const float* style_W = (const float*)d_in[3];
    const float* style_b = (const float*)d_in[4];
    const float* bias    = (const float*)d_in[5];
    float* out = (float*)d_out;

    prep1<<<768, 256>>>(w, style_W, style_b, weight);
    prep2<<<128, 256>>>();

    dim3 grid(HH, Bq);
    conv_mma_kernel<<<grid, 512>>>(x, bias, out);
}

// round 17
// speedup vs baseline: 1.1363x; 1.1363x over previous
#include <cuda_runtime.h>
#include <cuda_fp16.h>
#include <cstdint>

#define Bq    8
#define CIN   128
#define COUT  128
#define HH    256
#define WW    256
#define SDIM  512

#define PXW   68     // words (half2) per px row; row stride 272B == 16 mod 128 -> LDSM conflict-free
#define NPX   130    // 128 px + 2 halo

__device__ float  g_style[Bq * CIN];
__device__ float  g_demod[Bq * COUT];
__device__ float  g_W2[COUT * CIN];
__device__ __half g_wA[36 * 4096];   // fragment-ordered fp16 weights (exact size)

#define MMA_F16(d, a, bb)                                                 \
    asm volatile("mma.sync.aligned.m16n8k16.row.col.f32.f16.f16.f32 "     \
                 "{%0,%1,%2,%3}, {%4,%5,%6,%7}, {%8,%9}, {%0,%1,%2,%3};"  \
                 : "+f"((d)[0]), "+f"((d)[1]), "+f"((d)[2]), "+f"((d)[3]) \
                 : "r"((a)[0]), "r"((a)[1]), "r"((a)[2]), "r"((a)[3]),    \
                   "r"((bb)[0]), "r"((bb)[1]))

#define LDSM_X4(r0, r1, r2, r3, addr)                                     \
    asm volatile("ldmatrix.sync.aligned.m8n8.x4.shared.b16 "              \
                 "{%0,%1,%2,%3}, [%4];"                                   \
                 : "=r"(r0), "=r"(r1), "=r"(r2), "=r"(r3) : "r"(addr))

// ---------------------------------------------------------------------------
// prep1: blocks 0..127 style GEMV; 128..191 W2; 192..767 weight prepack.
// ---------------------------------------------------------------------------
__global__ void prep1(const float* __restrict__ w,
                      const float* __restrict__ style_W,
                      const float* __restrict__ style_b,
                      const float* __restrict__ weight) {
    if (blockIdx.x < 128) {
        const int gw   = blockIdx.x * 8 + (threadIdx.x >> 5);
        const int lane = threadIdx.x & 31;
        const int b = gw >> 7, o = gw & 127;
        const float4* wv = (const float4*)(w + (size_t)b * SDIM);
        const float4* Wv = (const float4*)(style_W + (size_t)o * SDIM);
        float acc = 0.f;
        #pragma unroll
        for (int k = 0; k < 4; k++) {
            float4 a = wv[lane + k * 32], c = Wv[lane + k * 32];
            acc += a.x * c.x + a.y * c.y + a.z * c.z + a.w * c.w;
        }
        #pragma unroll
        for (int d = 16; d > 0; d >>= 1)
            acc += __shfl_xor_sync(0xffffffffu, acc, d);
        if (lane == 0) g_style[b * CIN + o] = acc + style_b[o];
    } else if (blockIdx.x < 192) {
        int idx = (blockIdx.x - 128) * 256 + threadIdx.x;
        const float* p = weight + (size_t)idx * 9;
        float s = 0.f;
        #pragma unroll
        for (int t = 0; t < 9; t++) { float v = p[t]; s += v * v; }
        g_W2[idx] = s;
    } else {
        int idx = (blockIdx.x - 192) * 256 + threadIdx.x;   // < 147456 exactly
        int h    = idx & 1;
        int j    = (idx >> 1) & 3;
        int lane = (idx >> 3) & 31;
        int mt   = (idx >> 8) & 7;
        int kk   = (idx >> 11) & 1;
        int s    = idx >> 12;                               // 0..35
        int dx = s % 3;
        int g  = s / 3;
        int dy = g >> 2, chunk = g & 3;
        int m  = mt * 16 + (lane >> 2) + 8 * (j & 1);
        int kl = kk * 16 + (lane & 3) * 2 + 8 * (j >> 1) + h;
        int c  = chunk * 32 + kl;
        g_wA[idx] = __float2half_rn(weight[((size_t)m * CIN + c) * 9 + dy * 3 + dx]);
    }
}

// ---------------------------------------------------------------------------
// prep2: demod only
// ---------------------------------------------------------------------------
__global__ void prep2(void) {
    int gw   = blockIdx.x * 8 + (threadIdx.x >> 5);
    int lane = threadIdx.x & 31;
    int b = gw >> 7, o = gw & 127;
    float sum = 0.f;
    #pragma unroll
    for (int j = 0; j < 4; j++) {
        int i = lane + j * 32;
        float s = g_style[b * CIN + i];
        sum += s * s * g_W2[o * CIN + i];
    }
    #pragma unroll
    for (int d = 16; d > 0; d >>= 1)
        sum += __shfl_xor_sync(0xffffffffu, sum, d);
    if (lane == 0) g_demod[b * COUT + o] = rsqrtf(sum + 1e-8f);
}

// ---------------------------------------------------------------------------
// main conv: CTA = (xhalf, y, b). M=128 x N=128 x K=1152, fp16 m16n8k16.
// 8 warps = 2(wm) x 4(wn). 3 dy-groups, full 128 channels. 2 CTAs/SM.
// A software-pipelined one kk ahead; B via 2x ldmatrix.x4 per kk.
// ---------------------------------------------------------------------------
__global__ __launch_bounds__(256, 2)
void conv_mma_kernel(const float* __restrict__ x,
                     const float* __restrict__ bias,
                     float* __restrict__ out) {
    __shared__ float styl[CIN];
    __shared__ __align__(16) uint32_t stage[2][NPX * PXW];

    const int tid  = threadIdx.x;
    const int lane = tid & 31;
    const int warp = tid >> 5;
    const int wm   = warp >> 2;      // 0..1
    const int wn   = warp & 3;       // 0..3
    const int xh   = blockIdx.x;
    const int y    = blockIdx.y;
    const int b    = blockIdx.z;
    const int x0   = xh * 128;

    const int gid = lane >> 2;
    const int tig = lane & 3;

    if (tid < CIN) styl[tid] = g_style[b * CIN + tid];
    __syncthreads();

    float acc[4][4][4];
    #pragma unroll
    for (int m = 0; m < 4; m++)
        #pragma unroll
        for (int n = 0; n < 4; n++)
            #pragma unroll
            for (int j = 0; j < 4; j++) acc[m][n][j] = 0.f;

    // fill mapping: px = jj*64 + (tid>>2), cp = (tid&3) + 4*ii (ii 0..15)
    const int fpx = tid >> 2;
    const int fc  = tid & 3;
    const int tpx = 128 + (warp >> 1);
    const int tcp = (warp & 1) * 32 + lane;

    // ---- fill one stage buffer for group dy: 128 ch x 130 px ----
    auto fill = [&](int dy, uint32_t* buf) {
        const int yr = y + dy - 1;
        const bool yok = (unsigned)yr < (unsigned)HH;
        const float* xp = x + (((size_t)b * CIN) * HH + yr) * WW;
        #pragma unroll
        for (int jj = 0; jj < 2; jj++) {
            const int px = jj * 64 + fpx;
            const int gx = x0 - 1 + px;
            const bool ok = yok && ((unsigned)gx < (unsigned)WW);
            #pragma unroll
            for (int ii = 0; ii < 16; ii++) {
                const int cp = fc + ii * 4;
                float v0 = 0.f, v1 = 0.f;
                if (ok) {
                    v0 = __ldg(xp + (size_t)(2 * cp)     * HH * WW + gx) * styl[2 * cp];
                    v1 = __ldg(xp + (size_t)(2 * cp + 1) * HH * WW + gx) * styl[2 * cp + 1];
                }
                __half2 hv = __floats2half2_rn(v0, v1);
                buf[px * PXW + cp] = *(uint32_t*)&hv;
            }
        }
        if (warp < 4) {
            const int gx = x0 - 1 + tpx;
            float v0 = 0.f, v1 = 0.f;
            if (yok && gx < WW) {
                v0 = __ldg(xp + (size_t)(2 * tcp)     * HH * WW + gx) * styl[2 * tcp];
                v1 = __ldg(xp + (size_t)(2 * tcp + 1) * HH * WW + gx) * styl[2 * tcp + 1];
            }
            __half2 hv = __floats2half2_rn(v0, v1);
            buf[tpx * PXW + tcp] = *(uint32_t*)&hv;
        }
    };

    // A-fragment pointer for (dy, dx, kk)
    auto Aptr = [&](int dy, int dx, int kk) -> const uint4* {
        const int s = (dy * 4 + (kk >> 1)) * 3 + dx;
        return ((const uint4*)g_wA) +
               (((size_t)(s * 2 + (kk & 1)) * 8 + wm * 4) * 32 + lane);
    };

    // ---- one dx-step: A prefetched one kk ahead; B via ldmatrix.x4 ----
    // LDSM lane->row map: lanes 0-7 (n-tile0, k-lo), 8-15 (n-tile0, k-hi),
    //                     16-23 (n-tile1, k-lo), 24-31 (n-tile1, k-hi).
    auto compute = [&](const uint32_t* stg, int dy, int dx) {
        const uint32_t sb = (uint32_t)__cvta_generic_to_shared(stg);
        const uint32_t rowb = sb +
            (uint32_t)((wn * 32 + (lane & 7) + (((lane >> 4) & 1) << 3) + dx) * (PXW * 4)) +
            (uint32_t)(((lane >> 3) & 1) << 4);
        uint4 af[4];
        {
            const uint4* As = Aptr(dy, dx, 0);
            #pragma unroll
            for (int m = 0; m < 4; m++) af[m] = __ldg(As + m * 32);
        }
        #pragma unroll
        for (int kk = 0; kk < 8; kk++) {
            uint4 afn[4];
            if (kk < 7) {
                const uint4* As = Aptr(dy, dx, kk + 1);
                #pragma unroll
                for (int m = 0; m < 4; m++) afn[m] = __ldg(As + m * 32);
            }
            uint32_t bb[8];
            LDSM_X4(bb[0], bb[1], bb[2], bb[3], rowb + kk * 32);               // n-tiles 0,1
            LDSM_X4(bb[4], bb[5], bb[6], bb[7], rowb + 16 * PXW * 4 + kk * 32); // n-tiles 2,3
            #pragma unroll
            for (int m = 0; m < 4; m++) {
                const uint32_t* a = (const uint32_t*)&af[m];
                MMA_F16(acc[m][0], a, (bb + 0));
                MMA_F16(acc[m][1], a, (bb + 2));
                MMA_F16(acc[m][2], a, (bb + 4));
                MMA_F16(acc[m][3], a, (bb + 6));
            }
            if (kk < 7) {
                #pragma unroll
                for (int m = 0; m < 4; m++) af[m] = afn[m];
            }
        }
    };

    fill(0, stage[0]);
    __syncthreads();

    #pragma unroll 1
    for (int G = 0; G < 3; G++) {
        const int cur = G & 1;
        compute(stage[cur], G, 0);
        if (G < 2) fill(G + 1, stage[cur ^ 1]);
        compute(stage[cur], G, 1);
        compute(stage[cur], G, 2);
        if (G < 2) __syncthreads();
    }

    // ---- epilogue: demod + bias, float2 stores ----
    #pragma unroll
    for (int m = 0; m < 4; m++) {
        const int oc0 = (wm * 4 + m) * 16 + gid;
        const int oc1 = oc0 + 8;
        const float d0 = g_demod[b * COUT + oc0], bb0 = bias[oc0];
        const float d1 = g_demod[b * COUT + oc1], bb1 = bias[oc1];
        float* r0 = out + (((size_t)b * COUT + oc0) * HH + y) * WW;
        float* r1 = out + (((size_t)b * COUT + oc1) * HH + y) * WW;
        #pragma unroll
        for (int n = 0; n < 4; n++) {
            const int px = x0 + (wn * 4 + n) * 8 + tig * 2;
            float2 v0 = make_float2(acc[m][n][0] * d0 + bb0, acc[m][n][1] * d0 + bb0);
            float2 v1 = make_float2(acc[m][n][2] * d1 + bb1, acc[m][n][3] * d1 + bb1);
            *(float2*)(r0 + px) = v0;
            *(float2*)(r1 + px) = v1;
        }
    }
}

// ---------------------------------------------------------------------------
extern "C" void kernel_launch(void* const* d_in, const int* in_sizes, int n_in,
                              void* d_out, int out_size) {
    const float* x       = (const float*)d_in[0];
    const float* w       = (const float*)d_in[1];
    const float* weight  = (const float*)d_in[2];
    const float* style_W = (const float*)d_in[3];
    const float* style_b = (const float*)d_in[4];
    const float* bias    = (const float*)d_in[5];
    float* out = (float*)d_out;

    prep1<<<768, 256>>>(w, style_W, style_b, weight);
    prep2<<<128, 256>>>();

    dim3 grid(2, HH, Bq);
    conv_mma_kernel<<<grid, 256>>>(x, bias, out);
}